// round 4
// baseline (speedup 1.0000x reference)
#include <cuda_runtime.h>
#include <math.h>

#define DD 8
#define BB 4096
#define VV 1024
#define KSEL 102
#define ROWS (DD * BB)
#define FULLM 0xFFFFFFFFu

__device__ int g_samples[ROWS];

static __device__ __forceinline__ unsigned key_of(float x) {
    unsigned u = __float_as_uint(x);
    return (u & 0x80000000u) ? ~u : (u | 0x80000000u);
}
static __device__ __forceinline__ float inv_key(unsigned k) {
    return __uint_as_float((k & 0x80000000u) ? (k & 0x7FFFFFFFu) : ~k);
}

__global__ void __launch_bounds__(256, 4)
decode_kernel(const float* __restrict__ logits,
              const float* __restrict__ uni,
              const int*   __restrict__ curv,
              float*       __restrict__ probs_out,
              int write_probs)
{
    __shared__ unsigned skeys[8][VV];   // 32 KB: per-warp key rows
    __shared__ unsigned hist[8][256];   //  8 KB: per-warp histograms

    const int warp = threadIdx.x >> 5;
    const int lane = threadIdx.x & 31;
    const int row  = blockIdx.x * 8 + warp;
    const float* lrow = logits + (size_t)row * VV;
    const float* urow = uni    + (size_t)row * VV;
    const int cv = curv[row];
    unsigned* h  = hist[warp];
    unsigned* sk = skeys[warp];

    // ---- load phase: logits -> masked keys -> smem; hist pass 1; warp max ----
    #pragma unroll
    for (int i = 0; i < 8; i++) h[i * 32 + lane] = 0;
    __syncwarp();

    unsigned mk = 0;
    #pragma unroll
    for (int i = 0; i < 8; i++) {
        float4 l4 = ((const float4*)lrow)[i * 32 + lane];
        int g = (i * 32 + lane) * 4;
        float v0 = (g + 0 < cv || g == 0) ? -INFINITY : l4.x;
        float v1 = (g + 1 < cv)           ? -INFINITY : l4.y;
        float v2 = (g + 2 < cv)           ? -INFINITY : l4.z;
        float v3 = (g + 3 < cv)           ? -INFINITY : l4.w;
        unsigned k0 = key_of(v0), k1 = key_of(v1), k2 = key_of(v2), k3 = key_of(v3);
        ((uint4*)sk)[i * 32 + lane] = make_uint4(k0, k1, k2, k3);
        atomicAdd(&h[k0 >> 24], 1u);
        atomicAdd(&h[k1 >> 24], 1u);
        atomicAdd(&h[k2 >> 24], 1u);
        atomicAdd(&h[k3 >> 24], 1u);
        mk = max(mk, max(max(k0, k1), max(k2, k3)));
    }
    __syncwarp();
    mk = __reduce_max_sync(FULLM, mk);
    const float rowmax = inv_key(mk);

    // ---- scan pass 1: find top-byte bin b1 and remaining rank kk2 ----
    int b1, kk2;
    {
        unsigned v[8]; unsigned tot = 0;
        #pragma unroll
        for (int i = 0; i < 8; i++) { v[i] = h[lane * 8 + i]; tot += v[i]; }
        unsigned suf = tot;
        #pragma unroll
        for (int off = 1; off < 32; off <<= 1) {
            unsigned t = __shfl_down_sync(FULLM, suf, off);
            if (lane + off < 32) suf += t;
        }
        unsigned tail = suf - tot;
        int fi = -1; unsigned fnext = 0;
        unsigned run = tail;
        #pragma unroll
        for (int i = 7; i >= 0; i--) {
            unsigned Snext = run;
            run += v[i];
            if ((int)run >= KSEL && (int)Snext < KSEL) { fi = i; fnext = Snext; }
        }
        unsigned bal = __ballot_sync(FULLM, fi >= 0);
        int src = __ffs(bal) - 1;
        b1  = __shfl_sync(FULLM, fi, src) + src * 8;
        kk2 = KSEL - (int)__shfl_sync(FULLM, fnext, src);
        // zero hist for pass 2
        #pragma unroll
        for (int i = 0; i < 8; i++) h[lane * 8 + i] = 0;
    }
    __syncwarp();

    // ---- hist pass 2 over bits 23:16 (keys from smem) ----
    #pragma unroll
    for (int i = 0; i < 8; i++) {
        uint4 k4 = ((const uint4*)sk)[i * 32 + lane];
        if ((int)(k4.x >> 24) == b1) atomicAdd(&h[(k4.x >> 16) & 0xFFu], 1u);
        if ((int)(k4.y >> 24) == b1) atomicAdd(&h[(k4.y >> 16) & 0xFFu], 1u);
        if ((int)(k4.z >> 24) == b1) atomicAdd(&h[(k4.z >> 16) & 0xFFu], 1u);
        if ((int)(k4.w >> 24) == b1) atomicAdd(&h[(k4.w >> 16) & 0xFFu], 1u);
    }
    __syncwarp();

    int b2, kk3, c2;
    {
        unsigned v[8]; unsigned tot = 0;
        #pragma unroll
        for (int i = 0; i < 8; i++) { v[i] = h[lane * 8 + i]; tot += v[i]; }
        unsigned suf = tot;
        #pragma unroll
        for (int off = 1; off < 32; off <<= 1) {
            unsigned t = __shfl_down_sync(FULLM, suf, off);
            if (lane + off < 32) suf += t;
        }
        unsigned tail = suf - tot;
        int fi = -1; unsigned fnext = 0, fcnt = 0;
        unsigned run = tail;
        #pragma unroll
        for (int i = 7; i >= 0; i--) {
            unsigned Snext = run;
            run += v[i];
            if ((int)run >= kk2 && (int)Snext < kk2) { fi = i; fnext = Snext; fcnt = v[i]; }
        }
        unsigned bal = __ballot_sync(FULLM, fi >= 0);
        int src = __ffs(bal) - 1;
        b2  = __shfl_sync(FULLM, fi, src) + src * 8;
        kk3 = kk2 - (int)__shfl_sync(FULLM, fnext, src);
        c2  = (int)__shfl_sync(FULLM, fcnt, src);
    }

    const unsigned P16 = ((unsigned)b1 << 8) | (unsigned)b2;
    unsigned T;
    if (c2 == kk3) {
        T = P16 << 16;                      // whole 16-bit bin kept (fast path)
    } else {
        unsigned cur = 0xFFFFFFFFu;
        int rem = kk3;
        while (rem > 0) {
            unsigned m = 0;
            int c = 0;
            #pragma unroll
            for (int i = 0; i < 8; i++) {
                uint4 k4 = ((const uint4*)sk)[i * 32 + lane];
                unsigned ks[4] = {k4.x, k4.y, k4.z, k4.w};
                #pragma unroll
                for (int j = 0; j < 4; j++) {
                    unsigned k = ks[j];
                    if ((k >> 16) == P16 && k < cur) m = max(m, k);
                }
            }
            m = __reduce_max_sync(FULLM, m);
            #pragma unroll
            for (int i = 0; i < 8; i++) {
                uint4 k4 = ((const uint4*)sk)[i * 32 + lane];
                c += (k4.x == m) + (k4.y == m) + (k4.z == m) + (k4.w == m);
            }
            c = __reduce_add_sync(FULLM, c);
            rem -= c;
            cur = m;
        }
        T = cur;
    }

    // ---- sum of exp over kept (cheap __expf; logZ is a common row constant) ----
    float s = 0.0f;
    #pragma unroll
    for (int i = 0; i < 8; i++) {
        uint4 k4 = ((const uint4*)sk)[i * 32 + lane];
        unsigned ks[4] = {k4.x, k4.y, k4.z, k4.w};
        #pragma unroll
        for (int j = 0; j < 4; j++) {
            float ex = __expf(inv_key(ks[j]) - rowmax);
            s += (ks[j] >= T) ? ex : 0.0f;
        }
    }
    #pragma unroll
    for (int off = 16; off > 0; off >>= 1)
        s += __shfl_xor_sync(FULLM, s, off);
    const float logZ = logf(s);

    // ---- fused probs write + gumbel-max (u loaded only for kept elements) ----
    float bestv = -INFINITY;
    int   besti = VV;
    float* prow = probs_out + (size_t)row * VV;
    #pragma unroll
    for (int i = 0; i < 8; i++) {
        uint4 k4 = ((const uint4*)sk)[i * 32 + lane];
        unsigned ks[4] = {k4.x, k4.y, k4.z, k4.w};
        float o[4];
        #pragma unroll
        for (int j = 0; j < 4; j++) {
            bool kept = ks[j] >= T;
            float lp = (inv_key(ks[j]) - rowmax) - logZ;
            o[j] = kept ? __expf(lp) : 0.0f;
            if (kept) {
                int g = (i * 32 + lane) * 4 + j;
                float uu  = __ldg(urow + g);
                float gum = -logf(-logf(uu + 1e-20f) + 1e-20f);
                float sc  = lp + gum;
                if (sc > bestv || (sc == bestv && g < besti)) { bestv = sc; besti = g; }
            }
        }
        if (write_probs)
            ((float4*)prow)[i * 32 + lane] = make_float4(o[0], o[1], o[2], o[3]);
    }

    // ---- warp argmax (first-index tie break) ----
    #pragma unroll
    for (int off = 16; off > 0; off >>= 1) {
        float ov = __shfl_xor_sync(FULLM, bestv, off);
        int   oi = __shfl_xor_sync(FULLM, besti, off);
        if (ov > bestv || (ov == bestv && oi < besti)) { bestv = ov; besti = oi; }
    }
    if (lane == 0) g_samples[row] = besti;
}

// tokens[b*DD + d] = (d==0 || samples[0][b]==NOTE_TYPE) ? samples[d][b] : 0
__global__ void tokens_kernel(float* __restrict__ out)
{
    int i = blockIdx.x * blockDim.x + threadIdx.x;
    if (i >= BB * DD) return;
    int b = i / DD;
    int d = i % DD;
    int s0 = g_samples[b];
    int sd = g_samples[d * BB + b];
    int tok = (d == 0 || s0 == 1) ? sd : 0;
    out[i] = (float)tok;
}

extern "C" void kernel_launch(void* const* d_in, const int* in_sizes, int n_in,
                              void* d_out, int out_size)
{
    const float* logits = (const float*)d_in[0];
    const float* u      = (const float*)d_in[1];
    const int*   cv     = (const int*)d_in[2];
    float* out = (float*)d_out;

    const long long n_probs  = (long long)DD * BB * VV;
    const long long n_tokens = (long long)BB * DD;

    float* tok_ptr   = nullptr;
    float* probs_ptr = nullptr;
    if ((long long)out_size == n_probs + n_tokens) {
        tok_ptr   = out;
        probs_ptr = out + n_tokens;
    } else if ((long long)out_size == n_probs) {
        probs_ptr = out;
    } else {
        tok_ptr = out;
    }

    decode_kernel<<<ROWS / 8, 256>>>(logits, u, cv,
                                     probs_ptr, probs_ptr != nullptr ? 1 : 0);
    if (tok_ptr != nullptr) {
        tokens_kernel<<<(BB * DD + 255) / 256, 256>>>(tok_ptr);
    }
}

// round 5
// speedup vs baseline: 1.5597x; 1.5597x over previous
#include <cuda_runtime.h>
#include <math.h>

#define DD 8
#define BB 4096
#define VV 1024
#define KSEL 102
#define ROWS (DD * BB)
#define FULLM 0xFFFFFFFFu

__device__ int g_samples[ROWS];

static __device__ __forceinline__ unsigned key_of(float x) {
    unsigned u = __float_as_uint(x);
    return (u & 0x80000000u) ? ~u : (u | 0x80000000u);
}
static __device__ __forceinline__ float inv_key(unsigned k) {
    return __uint_as_float((k & 0x80000000u) ? (k & 0x7FFFFFFFu) : ~k);
}

// suffix-scan a 256-bin per-warp histogram; find bin containing rank kk (from top)
static __device__ __forceinline__ void scan_hist(const unsigned* h, int lane, int kk,
                                                 int& bin, int& krem, int& cnt)
{
    unsigned v[8]; unsigned tot = 0;
    #pragma unroll
    for (int i = 0; i < 8; i++) { v[i] = h[lane * 8 + i]; tot += v[i]; }
    unsigned suf = tot;
    #pragma unroll
    for (int off = 1; off < 32; off <<= 1) {
        unsigned t = __shfl_down_sync(FULLM, suf, off);
        if (lane + off < 32) suf += t;
    }
    unsigned tail = suf - tot;               // sum over lanes > lane
    int fi = -1; unsigned fnext = 0, fcnt = 0;
    unsigned run = tail;
    #pragma unroll
    for (int i = 7; i >= 0; i--) {
        unsigned Snext = run;
        run += v[i];
        if ((int)run >= kk && (int)Snext < kk) { fi = i; fnext = Snext; fcnt = v[i]; }
    }
    unsigned bal = __ballot_sync(FULLM, fi >= 0);
    int src = __ffs(bal) - 1;
    bin  = __shfl_sync(FULLM, fi, src) + src * 8;
    krem = kk - (int)__shfl_sync(FULLM, fnext, src);
    cnt  = (int)__shfl_sync(FULLM, fcnt, src);
}

__global__ void __launch_bounds__(256, 4)
decode_kernel(const float* __restrict__ logits,
              const float* __restrict__ uni,
              const int*   __restrict__ curv,
              float*       __restrict__ probs_out,
              int write_probs)
{
    __shared__ float    sexs[8][VV];    // 32 KB: per-warp exp values
    __shared__ unsigned hist[8][256];   //  8 KB: per-warp histograms

    const int warp = threadIdx.x >> 5;
    const int lane = threadIdx.x & 31;
    const int row  = blockIdx.x * 8 + warp;
    const float* lrow = logits + (size_t)row * VV;
    const float* urow = uni    + (size_t)row * VV;
    const int cv = curv[row];
    unsigned* h  = hist[warp];
    float*    sx = sexs[warp];

    #pragma unroll
    for (int i = 0; i < 8; i++) h[i * 32 + lane] = 0;
    __syncwarp();

    // ---- pass A (read 1): hist over top byte + rowmax + packed 16-bit prefixes ----
    unsigned pp[16];                 // 2 prefixes per register
    unsigned mk = 0;
    #pragma unroll
    for (int i = 0; i < 8; i++) {
        float4 l4 = ((const float4*)lrow)[i * 32 + lane];
        int g = (i * 32 + lane) * 4;
        float v0 = (g + 0 < cv || g == 0) ? -INFINITY : l4.x;
        float v1 = (g + 1 < cv)           ? -INFINITY : l4.y;
        float v2 = (g + 2 < cv)           ? -INFINITY : l4.z;
        float v3 = (g + 3 < cv)           ? -INFINITY : l4.w;
        unsigned k0 = key_of(v0), k1 = key_of(v1), k2 = key_of(v2), k3 = key_of(v3);
        atomicAdd(&h[k0 >> 24], 1u);
        atomicAdd(&h[k1 >> 24], 1u);
        atomicAdd(&h[k2 >> 24], 1u);
        atomicAdd(&h[k3 >> 24], 1u);
        mk = max(mk, max(max(k0, k1), max(k2, k3)));
        pp[2 * i + 0] = (k0 >> 16) | (k1 & 0xFFFF0000u);
        pp[2 * i + 1] = (k2 >> 16) | (k3 & 0xFFFF0000u);
    }
    __syncwarp();
    mk = __reduce_max_sync(FULLM, mk);
    const float rowmax = inv_key(mk);

    // ---- scan pass 1 ----
    int b1, kk2, c1;
    scan_hist(h, lane, KSEL, b1, kk2, c1);
    #pragma unroll
    for (int i = 0; i < 8; i++) h[lane * 8 + i] = 0;
    __syncwarp();

    // ---- hist pass 2 from stored prefixes ----
    #pragma unroll
    for (int q = 0; q < 16; q++) {
        unsigned pa = pp[q] & 0xFFFFu;
        unsigned pb = pp[q] >> 16;
        if ((int)(pa >> 8) == b1) atomicAdd(&h[pa & 0xFFu], 1u);
        if ((int)(pb >> 8) == b1) atomicAdd(&h[pb & 0xFFu], 1u);
    }
    __syncwarp();

    int b2, kk3, c2;
    scan_hist(h, lane, kk2, b2, kk3, c2);

    const unsigned P16 = ((unsigned)b1 << 8) | (unsigned)b2;
    unsigned T;
    if (c2 == kk3) {
        T = P16 << 16;                       // whole 16-bit bin kept (fast path)
    } else {
        // exact kth among elements with this 16-bit prefix (scalar L1-hot reloads)
        unsigned cur = 0xFFFFFFFFu;
        int rem = kk3;
        while (rem > 0) {
            unsigned m = 0;
            #pragma unroll
            for (int e = 0; e < 32; e++) {
                unsigned p = (e & 1) ? (pp[e >> 1] >> 16) : (pp[e >> 1] & 0xFFFFu);
                if (p == P16) {
                    int g = (e >> 2) * 128 + lane * 4 + (e & 3);
                    float val = __ldg(lrow + g);
                    if (g < cv || g == 0) val = -INFINITY;
                    unsigned k = key_of(val);
                    if (k < cur) m = max(m, k);
                }
            }
            m = __reduce_max_sync(FULLM, m);
            int c = 0;
            #pragma unroll
            for (int e = 0; e < 32; e++) {
                unsigned p = (e & 1) ? (pp[e >> 1] >> 16) : (pp[e >> 1] & 0xFFFFu);
                if (p == P16) {
                    int g = (e >> 2) * 128 + lane * 4 + (e & 3);
                    float val = __ldg(lrow + g);
                    if (g < cv || g == 0) val = -INFINITY;
                    c += (key_of(val) == m) ? 1 : 0;
                }
            }
            c = __reduce_add_sync(FULLM, c);
            rem -= c;
            cur = m;
        }
        T = cur;
    }

    // ---- pass C (read 2): kept mask + sum-exp + store exp values to smem ----
    float s = 0.0f;
    unsigned km = 0;
    #pragma unroll
    for (int i = 0; i < 8; i++) {
        float4 l4 = ((const float4*)lrow)[i * 32 + lane];
        int g = (i * 32 + lane) * 4;
        float v0 = (g + 0 < cv || g == 0) ? -INFINITY : l4.x;
        float v1 = (g + 1 < cv)           ? -INFINITY : l4.y;
        float v2 = (g + 2 < cv)           ? -INFINITY : l4.z;
        float v3 = (g + 3 < cv)           ? -INFINITY : l4.w;
        float e0 = 0.f, e1 = 0.f, e2 = 0.f, e3 = 0.f;
        if (key_of(v0) >= T) { e0 = __expf(v0 - rowmax); s += e0; km |= 1u << (i * 4 + 0); }
        if (key_of(v1) >= T) { e1 = __expf(v1 - rowmax); s += e1; km |= 1u << (i * 4 + 1); }
        if (key_of(v2) >= T) { e2 = __expf(v2 - rowmax); s += e2; km |= 1u << (i * 4 + 2); }
        if (key_of(v3) >= T) { e3 = __expf(v3 - rowmax); s += e3; km |= 1u << (i * 4 + 3); }
        ((float4*)sx)[i * 32 + lane] = make_float4(e0, e1, e2, e3);
    }
    #pragma unroll
    for (int off = 16; off > 0; off >>= 1)
        s += __shfl_xor_sync(FULLM, s, off);
    const float logZ = logf(s);
    const float invZ = 1.0f / s;

    // ---- pass D: probs = ex * invZ (streamed from smem) ----
    if (write_probs) {
        float* prow = probs_out + (size_t)row * VV;
        #pragma unroll
        for (int i = 0; i < 8; i++) {
            float4 e4 = ((const float4*)sx)[i * 32 + lane];
            ((float4*)prow)[i * 32 + lane] =
                make_float4(e4.x * invZ, e4.y * invZ, e4.z * invZ, e4.w * invZ);
        }
    }

    // ---- gumbel-max over kept (ffs loop; lrow/urow L1-hot scalar loads) ----
    float bestv = -INFINITY;
    int   besti = VV;
    unsigned m = km;
    while (m) {
        int e = __ffs(m) - 1;
        m &= m - 1;
        int g = (e >> 2) * 128 + lane * 4 + (e & 3);
        float val = __ldg(lrow + g);
        float uu  = __ldg(urow + g);
        float lp  = (val - rowmax) - logZ;
        float gum = -logf(-logf(uu + 1e-20f) + 1e-20f);
        float sc  = lp + gum;
        if (sc > bestv || (sc == bestv && g < besti)) { bestv = sc; besti = g; }
    }
    #pragma unroll
    for (int off = 16; off > 0; off >>= 1) {
        float ov = __shfl_xor_sync(FULLM, bestv, off);
        int   oi = __shfl_xor_sync(FULLM, besti, off);
        if (ov > bestv || (ov == bestv && oi < besti)) { bestv = ov; besti = oi; }
    }
    if (lane == 0) g_samples[row] = besti;
}

// tokens[b*DD + d] = (d==0 || samples[0][b]==NOTE_TYPE) ? samples[d][b] : 0
__global__ void tokens_kernel(float* __restrict__ out)
{
    int i = blockIdx.x * blockDim.x + threadIdx.x;
    if (i >= BB * DD) return;
    int b = i / DD;
    int d = i % DD;
    int s0 = g_samples[b];
    int sd = g_samples[d * BB + b];
    int tok = (d == 0 || s0 == 1) ? sd : 0;
    out[i] = (float)tok;
}

extern "C" void kernel_launch(void* const* d_in, const int* in_sizes, int n_in,
                              void* d_out, int out_size)
{
    const float* logits = (const float*)d_in[0];
    const float* u      = (const float*)d_in[1];
    const int*   cv     = (const int*)d_in[2];
    float* out = (float*)d_out;

    const long long n_probs  = (long long)DD * BB * VV;
    const long long n_tokens = (long long)BB * DD;

    float* tok_ptr   = nullptr;
    float* probs_ptr = nullptr;
    if ((long long)out_size == n_probs + n_tokens) {
        tok_ptr   = out;
        probs_ptr = out + n_tokens;
    } else if ((long long)out_size == n_probs) {
        probs_ptr = out;
    } else {
        tok_ptr = out;
    }

    decode_kernel<<<ROWS / 8, 256>>>(logits, u, cv,
                                     probs_ptr, probs_ptr != nullptr ? 1 : 0);
    if (tok_ptr != nullptr) {
        tokens_kernel<<<(BB * DD + 255) / 256, 256>>>(tok_ptr);
    }
}